// round 6
// baseline (speedup 1.0000x reference)
#include <cuda_runtime.h>
#include <math.h>

#define NN 50000
#define NE 800000
#define HID 128
#define OUTC 64
#define GROWS 16

// ---------------- scratch (device globals; no allocation allowed) ----------------
__device__ float g_tmp[NN * HID];   // linear output (pre-aggregation)
__device__ float g_hbuf[NN * HID];  // h0 (post-relu, pre neighbor-mean)
__device__ float g_h0m[NN * HID];   // h0 after neighbor mean (JK input 0)
__device__ float g_h1[NN * HID];
__device__ float g_h2[NN * HID];
__device__ float g_dinv[NN];
__device__ int g_deg_in[NN];
__device__ int g_deg_out[NN];
__device__ int g_fill_in[NN];
__device__ int g_fill_out[NN];
__device__ int g_start_in[NN + 1];
__device__ int g_start_out[NN + 1];
__device__ int g_src_in[NE];    // per target node: list of source nodes
__device__ int g_dst_out[NE];   // per source node: list of target nodes

// ---------------- CSR construction ----------------
__global__ void zero_k() {
    int i = blockIdx.x * blockDim.x + threadIdx.x;
    if (i < NN) {
        g_deg_in[i] = 0; g_deg_out[i] = 0;
        g_fill_in[i] = 0; g_fill_out[i] = 0;
    }
}

__global__ void count_k(const int* __restrict__ row, const int* __restrict__ col) {
    int e = blockIdx.x * blockDim.x + threadIdx.x;
    if (e < NE) {
        atomicAdd(&g_deg_in[col[e]], 1);
        atomicAdd(&g_deg_out[row[e]], 1);
    }
}

// single-block exclusive scan of both degree arrays (N=50000, 1024 threads, chunk 49)
__global__ void scan_k() {
    __shared__ int s[1024];
    const int tid = threadIdx.x;
    const int CH = (NN + 1023) / 1024;
    int lo = tid * CH;
    int hi = lo + CH; if (hi > NN) hi = NN; if (lo > NN) lo = NN;

    // ---- in-degrees ----
    {
        int sum = 0;
        for (int i = lo; i < hi; i++) sum += g_deg_in[i];
        s[tid] = sum; __syncthreads();
        for (int off = 1; off < 1024; off <<= 1) {
            int v = (tid >= off) ? s[tid - off] : 0;
            __syncthreads();
            s[tid] += v;
            __syncthreads();
        }
        int run = (tid > 0) ? s[tid - 1] : 0;
        for (int i = lo; i < hi; i++) { g_start_in[i] = run; run += g_deg_in[i]; }
        if (tid == 1023) g_start_in[NN] = run;
    }
    __syncthreads();
    // ---- out-degrees ----
    {
        int sum = 0;
        for (int i = lo; i < hi; i++) sum += g_deg_out[i];
        s[tid] = sum; __syncthreads();
        for (int off = 1; off < 1024; off <<= 1) {
            int v = (tid >= off) ? s[tid - off] : 0;
            __syncthreads();
            s[tid] += v;
            __syncthreads();
        }
        int run = (tid > 0) ? s[tid - 1] : 0;
        for (int i = lo; i < hi; i++) { g_start_out[i] = run; run += g_deg_out[i]; }
        if (tid == 1023) g_start_out[NN] = run;
    }
}

__global__ void fill_k(const int* __restrict__ row, const int* __restrict__ col) {
    int e = blockIdx.x * blockDim.x + threadIdx.x;
    if (e < NE) {
        int r = row[e], c = col[e];
        int p = g_start_in[c] + atomicAdd(&g_fill_in[c], 1);
        g_src_in[p] = r;
        int q = g_start_out[r] + atomicAdd(&g_fill_out[r], 1);
        g_dst_out[q] = c;
    }
}

__global__ void dinv_k() {
    int i = blockIdx.x * blockDim.x + threadIdx.x;
    if (i < NN) g_dinv[i] = rsqrtf((float)(g_deg_in[i] + 1));  // +1 self loop
}

// ---------------- GEMM: out[N,128] = in[N,128] @ W[128,128] ----------------
// K split into two halves of 64 so static shared stays under 48 KB.
__global__ void __launch_bounds__(128) gemm128_k(const float* __restrict__ in,
                                                 const float* __restrict__ W,
                                                 float* __restrict__ out) {
    __shared__ float Wt[HID][68];    // [col j][kk] transposed, padded (bank-friendly v4)
    __shared__ float xs[GROWS][64];  // [row r][kk]
    const int tid = threadIdx.x;     // output column j
    const int ntiles = (NN + GROWS - 1) / GROWS;

    for (int khalf = 0; khalf < 2; khalf++) {
        __syncthreads();  // previous half's compute done before Wt overwrite
        for (int idx = tid; idx < 64 * HID; idx += 128) {
            int kk = idx >> 7;
            int j = idx & 127;
            Wt[j][kk] = W[(khalf * 64 + kk) * HID + j];
        }
        for (int tile = blockIdx.x; tile < ntiles; tile += gridDim.x) {
            int row0 = tile * GROWS;
            __syncthreads();  // protect xs overwrite; also orders Wt load on first tile
            for (int idx = tid; idx < GROWS * 64; idx += 128) {
                int r = idx >> 6;
                int kk = idx & 63;
                int row = row0 + r;
                xs[r][kk] = (row < NN) ? in[row * HID + khalf * 64 + kk] : 0.f;
            }
            __syncthreads();
            float acc[GROWS];
#pragma unroll
            for (int r = 0; r < GROWS; r++) acc[r] = 0.f;
#pragma unroll
            for (int kk = 0; kk < 64; kk += 4) {
                float4 w4 = *(const float4*)&Wt[tid][kk];
#pragma unroll
                for (int r = 0; r < GROWS; r++) {
                    float4 x4 = *(const float4*)&xs[r][kk];
                    acc[r] = fmaf(x4.x, w4.x, acc[r]);
                    acc[r] = fmaf(x4.y, w4.y, acc[r]);
                    acc[r] = fmaf(x4.z, w4.z, acc[r]);
                    acc[r] = fmaf(x4.w, w4.w, acc[r]);
                }
            }
#pragma unroll
            for (int r = 0; r < GROWS; r++) {
                int row = row0 + r;
                if (row < NN) {
                    if (khalf == 0) out[row * HID + tid] = acc[r];
                    else            out[row * HID + tid] += acc[r];
                }
            }
        }
    }
}

// ---------------- GCN aggregation (gather): warp per node ----------------
// hout[i] = relu( dinv[i] * ( hin[i]*dinv[i] + sum_{j -> i} hin[j]*dinv[j] ) + b )
__global__ void agg_gcn_k(const float* __restrict__ hin,
                          const float* __restrict__ bias,
                          float* __restrict__ hout) {
    int w = (blockIdx.x * blockDim.x + threadIdx.x) >> 5;
    if (w >= NN) return;
    int lane = threadIdx.x & 31;
    const float4* in4 = (const float4*)hin;

    float di = g_dinv[w];
    float4 v = in4[w * 32 + lane];
    float4 acc = make_float4(v.x * di, v.y * di, v.z * di, v.w * di);

    int s = g_start_in[w];
    int e = g_start_in[w + 1];
#pragma unroll 4
    for (int p = s; p < e; p++) {
        int j = __ldg(&g_src_in[p]);
        float dj = g_dinv[j];
        float4 u = in4[j * 32 + lane];
        acc.x = fmaf(u.x, dj, acc.x);
        acc.y = fmaf(u.y, dj, acc.y);
        acc.z = fmaf(u.z, dj, acc.z);
        acc.w = fmaf(u.w, dj, acc.w);
    }
    float4 b = ((const float4*)bias)[lane];
    acc.x = fmaxf(fmaf(acc.x, di, b.x), 0.f);
    acc.y = fmaxf(fmaf(acc.y, di, b.y), 0.f);
    acc.z = fmaxf(fmaf(acc.z, di, b.z), 0.f);
    acc.w = fmaxf(fmaf(acc.w, di, b.w), 0.f);
    ((float4*)hout)[w * 32 + lane] = acc;
}

// ---------------- neighbor mean over out-edges: warp per node ----------------
__global__ void agg_mean_k(const float* __restrict__ hin, float* __restrict__ hout) {
    int w = (blockIdx.x * blockDim.x + threadIdx.x) >> 5;
    if (w >= NN) return;
    int lane = threadIdx.x & 31;
    const float4* in4 = (const float4*)hin;
    int s = g_start_out[w];
    int e = g_start_out[w + 1];
    if (e == s) {  // degree 0 -> keep own feature
        ((float4*)hout)[w * 32 + lane] = in4[w * 32 + lane];
        return;
    }
    float4 acc = make_float4(0.f, 0.f, 0.f, 0.f);
#pragma unroll 4
    for (int p = s; p < e; p++) {
        int j = __ldg(&g_dst_out[p]);
        float4 u = in4[j * 32 + lane];
        acc.x += u.x; acc.y += u.y; acc.z += u.z; acc.w += u.w;
    }
    float inv = 1.f / (float)(e - s);
    acc.x *= inv; acc.y *= inv; acc.z *= inv; acc.w *= inv;
    ((float4*)hout)[w * 32 + lane] = acc;
}

// ---------------- final: JK combine + [N,128]@[128,64] + bias ----------------
__global__ void __launch_bounds__(64) final_k(const float* __restrict__ h0,
                                              const float* __restrict__ h1,
                                              const float* __restrict__ h2,
                                              const float* __restrict__ jk,
                                              const float* __restrict__ fcW,
                                              const float* __restrict__ fcb,
                                              float* __restrict__ out) {
    __shared__ float Wt[OUTC][132];   // [j][k] transposed, padded
    __shared__ float xs[GROWS][HID];  // combined JK rows
    const int tid = threadIdx.x;      // output column j (0..63)

    float a0 = jk[0], a1 = jk[1], a2 = jk[2];
    float m = fmaxf(a0, fmaxf(a1, a2));
    float e0 = expf(a0 - m), e1 = expf(a1 - m), e2 = expf(a2 - m);
    float inv = 1.f / (e0 + e1 + e2);
    float w0 = e0 * inv, w1 = e1 * inv, w2 = e2 * inv;

    for (int idx = tid; idx < OUTC * HID; idx += 64) {
        int k = idx >> 6;
        int j = idx & 63;
        Wt[j][k] = fcW[k * OUTC + j];
    }

    const int ntiles = (NN + GROWS - 1) / GROWS;
    for (int tile = blockIdx.x; tile < ntiles; tile += gridDim.x) {
        int row0 = tile * GROWS;
        __syncthreads();  // xs overwrite + (first iter) Wt ready
        for (int idx = tid; idx < GROWS * HID; idx += 64) {
            int r = idx >> 7;
            int k = idx & 127;
            int row = row0 + r;
            xs[r][k] = (row < NN)
                ? w0 * h0[row * HID + k] + w1 * h1[row * HID + k] + w2 * h2[row * HID + k]
                : 0.f;
        }
        __syncthreads();
        float acc[GROWS];
#pragma unroll
        for (int r = 0; r < GROWS; r++) acc[r] = 0.f;
#pragma unroll
        for (int k = 0; k < HID; k += 4) {
            float4 w4 = *(const float4*)&Wt[tid][k];
#pragma unroll
            for (int r = 0; r < GROWS; r++) {
                float4 x4 = *(const float4*)&xs[r][k];
                acc[r] = fmaf(x4.x, w4.x, acc[r]);
                acc[r] = fmaf(x4.y, w4.y, acc[r]);
                acc[r] = fmaf(x4.z, w4.z, acc[r]);
                acc[r] = fmaf(x4.w, w4.w, acc[r]);
            }
        }
        float bj = fcb[tid];
#pragma unroll
        for (int r = 0; r < GROWS; r++) {
            int row = row0 + r;
            if (row < NN) out[row * OUTC + tid] = acc[r] + bj;
        }
    }
}

// ---------------- launch ----------------
extern "C" void kernel_launch(void* const* d_in, const int* in_sizes, int n_in,
                              void* d_out, int out_size) {
    const float* x    = (const float*)d_in[0];
    const int*   ei   = (const int*)d_in[1];
    const float* W1   = (const float*)d_in[2];
    const float* b1   = (const float*)d_in[3];
    const float* W2   = (const float*)d_in[4];
    const float* b2   = (const float*)d_in[5];
    const float* W3   = (const float*)d_in[6];
    const float* b3   = (const float*)d_in[7];
    const float* jkw  = (const float*)d_in[8];
    const float* fcW  = (const float*)d_in[9];
    const float* fcb  = (const float*)d_in[10];
    float* out = (float*)d_out;

    const int* row = ei;        // sources
    const int* col = ei + NE;   // targets

    const int nodeBlocks = (NN + 255) / 256;
    const int edgeBlocks = (NE + 255) / 256;
    const int aggBlocks  = (NN * 32 + 255) / 256;

    // CSR build
    zero_k<<<nodeBlocks, 256>>>();
    count_k<<<edgeBlocks, 256>>>(row, col);
    scan_k<<<1, 1024>>>();
    fill_k<<<edgeBlocks, 256>>>(row, col);
    dinv_k<<<nodeBlocks, 256>>>();

    float* tmp  = nullptr; cudaGetSymbolAddress((void**)&tmp,  g_tmp);
    float* hbuf = nullptr; cudaGetSymbolAddress((void**)&hbuf, g_hbuf);
    float* h0m  = nullptr; cudaGetSymbolAddress((void**)&h0m,  g_h0m);
    float* h1   = nullptr; cudaGetSymbolAddress((void**)&h1,   g_h1);
    float* h2   = nullptr; cudaGetSymbolAddress((void**)&h2,   g_h2);

    // layer 0
    gemm128_k<<<740, 128>>>(x, W1, tmp);
    agg_gcn_k<<<aggBlocks, 256>>>(tmp, b1, hbuf);
    agg_mean_k<<<aggBlocks, 256>>>(hbuf, h0m);
    // layer 1
    gemm128_k<<<740, 128>>>(h0m, W2, tmp);
    agg_gcn_k<<<aggBlocks, 256>>>(tmp, b2, h1);
    // layer 2
    gemm128_k<<<740, 128>>>(h1, W3, tmp);
    agg_gcn_k<<<aggBlocks, 256>>>(tmp, b3, h2);
    // JK + head
    final_k<<<740, 64>>>(h0m, h1, h2, jkw, fcW, fcb, out);
}

// round 7
// speedup vs baseline: 1.0918x; 1.0918x over previous
#include <cuda_runtime.h>
#include <math.h>

#define NN 50000
#define NE 800000
#define HID 128
#define OUTC 64

// ---------------- scratch (device globals; no allocation allowed) ----------------
__device__ float g_tmp[NN * HID];   // linear output (pre-aggregation, pre-scaled by dinv)
__device__ float g_hbuf[NN * HID];  // h0 (post-relu, pre neighbor-mean)
__device__ float g_h0m[NN * HID];   // h0 after neighbor mean (JK input 0)
__device__ float g_h1[NN * HID];
__device__ float g_h2[NN * HID];
__device__ float g_dinv[NN];
__device__ int g_deg_in[NN];
__device__ int g_deg_out[NN];
__device__ int g_fill_in[NN];
__device__ int g_fill_out[NN];
__device__ int g_start_in[NN + 1];
__device__ int g_start_out[NN + 1];
__device__ int g_src_in[NE];    // per target node: list of source nodes
__device__ int g_dst_out[NE];   // per source node: list of target nodes

// ---------------- packed f32x2 helpers (sm_103a FFMA2 via PTX) ----------------
__device__ __forceinline__ void ffma2(unsigned long long &d, unsigned long long a,
                                      unsigned long long b) {
    asm("fma.rn.f32x2 %0, %1, %2, %0;" : "+l"(d) : "l"(a), "l"(b));
}
__device__ __forceinline__ float red2(unsigned long long v) {
    float x, y;
    asm("mov.b64 {%0,%1}, %2;" : "=f"(x), "=f"(y) : "l"(v));
    return x + y;
}

// ---------------- CSR construction ----------------
__global__ void zero_k() {
    int i = blockIdx.x * blockDim.x + threadIdx.x;
    if (i < NN) {
        g_deg_in[i] = 0; g_deg_out[i] = 0;
        g_fill_in[i] = 0; g_fill_out[i] = 0;
    }
}

__global__ void count_k(const int* __restrict__ row, const int* __restrict__ col) {
    int e = blockIdx.x * blockDim.x + threadIdx.x;
    if (e < NE) {
        atomicAdd(&g_deg_in[col[e]], 1);
        atomicAdd(&g_deg_out[row[e]], 1);
    }
}

// single-block exclusive scan of both degree arrays; also computes dinv (fused)
__global__ void scan_k() {
    __shared__ int s[1024];
    const int tid = threadIdx.x;
    const int CH = (NN + 1023) / 1024;
    int lo = tid * CH;
    int hi = lo + CH; if (hi > NN) hi = NN; if (lo > NN) lo = NN;

    // ---- in-degrees (+ dinv) ----
    {
        int sum = 0;
        for (int i = lo; i < hi; i++) sum += g_deg_in[i];
        s[tid] = sum; __syncthreads();
        for (int off = 1; off < 1024; off <<= 1) {
            int v = (tid >= off) ? s[tid - off] : 0;
            __syncthreads();
            s[tid] += v;
            __syncthreads();
        }
        int run = (tid > 0) ? s[tid - 1] : 0;
        for (int i = lo; i < hi; i++) {
            int d = g_deg_in[i];
            g_start_in[i] = run; run += d;
            g_dinv[i] = rsqrtf((float)(d + 1));   // +1 self loop
        }
        if (tid == 1023) g_start_in[NN] = run;
    }
    __syncthreads();
    // ---- out-degrees ----
    {
        int sum = 0;
        for (int i = lo; i < hi; i++) sum += g_deg_out[i];
        s[tid] = sum; __syncthreads();
        for (int off = 1; off < 1024; off <<= 1) {
            int v = (tid >= off) ? s[tid - off] : 0;
            __syncthreads();
            s[tid] += v;
            __syncthreads();
        }
        int run = (tid > 0) ? s[tid - 1] : 0;
        for (int i = lo; i < hi; i++) { g_start_out[i] = run; run += g_deg_out[i]; }
        if (tid == 1023) g_start_out[NN] = run;
    }
}

__global__ void fill_k(const int* __restrict__ row, const int* __restrict__ col) {
    int e = blockIdx.x * blockDim.x + threadIdx.x;
    if (e < NE) {
        int r = row[e], c = col[e];
        int p = g_start_in[c] + atomicAdd(&g_fill_in[c], 1);
        g_src_in[p] = r;
        int q = g_start_out[r] + atomicAdd(&g_fill_out[r], 1);
        g_dst_out[q] = c;
    }
}

// ---------------- GEMM: out[N,128] = dinv[row] * (in[N,128] @ W[128,128]) -------
// 128 threads: col base cb = t&31 -> cols {cb, cb+32, cb+64, cb+96};
// row group rg = t>>5 -> rows [row0+8*rg, +8). Tile = 32 rows x 128 cols.
// K split in two halves of 64; FFMA2 pairs over K, horizontal add at end.
__global__ void __launch_bounds__(128) gemm128_k(const float* __restrict__ in,
                                                 const float* __restrict__ W,
                                                 float* __restrict__ out) {
    __shared__ float Wt[HID][68];   // [col j][kk] (K-major per column), 16B-aligned rows
    __shared__ float xs[32][68];    // [row r][kk]
    const int t = threadIdx.x;
    const int cb = t & 31;
    const int rg = t >> 5;
    const int ntiles = (NN + 31) / 32;

    for (int khalf = 0; khalf < 2; khalf++) {
        __syncthreads();  // previous half's compute done before Wt overwrite
        for (int idx = t; idx < 64 * HID; idx += 128) {
            int kk = idx >> 7;
            int j = idx & 127;
            Wt[j][kk] = W[(khalf * 64 + kk) * HID + j];
        }
        for (int tile = blockIdx.x; tile < ntiles; tile += gridDim.x) {
            int row0 = tile * 32;
            __syncthreads();  // xs overwrite; also orders Wt load on first tile
            for (int idx = t; idx < 32 * 16; idx += 128) {
                int r = idx >> 4;
                int k4 = idx & 15;
                int row = row0 + r;
                float4 v = (row < NN) ? ((const float4*)in)[row * 32 + khalf * 16 + k4]
                                      : make_float4(0.f, 0.f, 0.f, 0.f);
                *(float4*)&xs[r][k4 * 4] = v;
            }
            __syncthreads();

            unsigned long long acc[8][4];
#pragma unroll
            for (int r = 0; r < 8; r++)
#pragma unroll
                for (int m = 0; m < 4; m++) acc[r][m] = 0ull;

#pragma unroll
            for (int kk = 0; kk < 64; kk += 4) {
                ulonglong2 w2[4];
#pragma unroll
                for (int m = 0; m < 4; m++)
                    w2[m] = *(const ulonglong2*)&Wt[cb + 32 * m][kk];
#pragma unroll
                for (int r = 0; r < 8; r++) {
                    ulonglong2 xv = *(const ulonglong2*)&xs[rg * 8 + r][kk];
#pragma unroll
                    for (int m = 0; m < 4; m++) {
                        ffma2(acc[r][m], xv.x, w2[m].x);
                        ffma2(acc[r][m], xv.y, w2[m].y);
                    }
                }
            }
#pragma unroll
            for (int r = 0; r < 8; r++) {
                int row = row0 + rg * 8 + r;
                if (row < NN) {
                    float sc = g_dinv[row];
#pragma unroll
                    for (int m = 0; m < 4; m++) {
                        float v = red2(acc[r][m]) * sc;
                        int c = cb + 32 * m;
                        if (khalf == 0) out[row * HID + c] = v;
                        else            out[row * HID + c] += v;
                    }
                }
            }
        }
    }
}

// ---------------- GCN aggregation (gather): warp per node ----------------
// hin rows are already scaled by dinv[src]. hout[i] = relu( dinv[i]*(hin[i] + sum_j hin[j]) + b )
__global__ void agg_gcn_k(const float* __restrict__ hin,
                          const float* __restrict__ bias,
                          float* __restrict__ hout) {
    int w = (blockIdx.x * blockDim.x + threadIdx.x) >> 5;
    if (w >= NN) return;
    int lane = threadIdx.x & 31;
    const float4* in4 = (const float4*)hin;

    float di = g_dinv[w];
    float4 acc = in4[w * 32 + lane];   // self term (already * dinv[w])

    int s = g_start_in[w];
    int e = g_start_in[w + 1];
#pragma unroll 4
    for (int p = s; p < e; p++) {
        int j = __ldg(&g_src_in[p]);
        float4 u = in4[j * 32 + lane];
        acc.x += u.x; acc.y += u.y; acc.z += u.z; acc.w += u.w;
    }
    float4 b = ((const float4*)bias)[lane];
    acc.x = fmaxf(fmaf(acc.x, di, b.x), 0.f);
    acc.y = fmaxf(fmaf(acc.y, di, b.y), 0.f);
    acc.z = fmaxf(fmaf(acc.z, di, b.z), 0.f);
    acc.w = fmaxf(fmaf(acc.w, di, b.w), 0.f);
    ((float4*)hout)[w * 32 + lane] = acc;
}

// ---------------- neighbor mean over out-edges: warp per node ----------------
__global__ void agg_mean_k(const float* __restrict__ hin, float* __restrict__ hout) {
    int w = (blockIdx.x * blockDim.x + threadIdx.x) >> 5;
    if (w >= NN) return;
    int lane = threadIdx.x & 31;
    const float4* in4 = (const float4*)hin;
    int s = g_start_out[w];
    int e = g_start_out[w + 1];
    if (e == s) {  // degree 0 -> keep own feature
        ((float4*)hout)[w * 32 + lane] = in4[w * 32 + lane];
        return;
    }
    float4 acc = make_float4(0.f, 0.f, 0.f, 0.f);
#pragma unroll 4
    for (int p = s; p < e; p++) {
        int j = __ldg(&g_dst_out[p]);
        float4 u = in4[j * 32 + lane];
        acc.x += u.x; acc.y += u.y; acc.z += u.z; acc.w += u.w;
    }
    float inv = 1.f / (float)(e - s);
    acc.x *= inv; acc.y *= inv; acc.z *= inv; acc.w *= inv;
    ((float4*)hout)[w * 32 + lane] = acc;
}

// ---------------- final: JK combine + [N,128]@[128,64] + bias ----------------
// 128 threads: cb = t&15 -> cols {cb, +16, +32, +48}; rg = t>>4 -> rows [row0+8*rg,+8).
// Tile = 64 rows x 64 cols; K split in halves of 64.
__global__ void __launch_bounds__(128) final_k(const float* __restrict__ h0,
                                               const float* __restrict__ h1,
                                               const float* __restrict__ h2,
                                               const float* __restrict__ jk,
                                               const float* __restrict__ fcW,
                                               const float* __restrict__ fcb,
                                               float* __restrict__ out) {
    __shared__ float Wt[OUTC][68];
    __shared__ float xs[64][68];
    const int t = threadIdx.x;
    const int cb = t & 15;
    const int rg = t >> 4;
    const int ntiles = (NN + 63) / 64;

    float a0 = jk[0], a1 = jk[1], a2 = jk[2];
    float mx = fmaxf(a0, fmaxf(a1, a2));
    float e0 = expf(a0 - mx), e1 = expf(a1 - mx), e2 = expf(a2 - mx);
    float inv = 1.f / (e0 + e1 + e2);
    float w0 = e0 * inv, w1 = e1 * inv, w2 = e2 * inv;
    float bj = fcb[cb]; // used per-col below via +16m lookups
    (void)bj;

    for (int khalf = 0; khalf < 2; khalf++) {
        __syncthreads();
        for (int idx = t; idx < 64 * OUTC; idx += 128) {
            int kk = idx >> 6;
            int j = idx & 63;
            Wt[j][kk] = fcW[(khalf * 64 + kk) * OUTC + j];
        }
        for (int tile = blockIdx.x; tile < ntiles; tile += gridDim.x) {
            int row0 = tile * 64;
            __syncthreads();
            for (int idx = t; idx < 64 * 64; idx += 128) {
                int r = idx >> 6;
                int k = idx & 63;
                int row = row0 + r;
                int g = row * HID + khalf * 64 + k;
                xs[r][k] = (row < NN)
                    ? w0 * h0[g] + w1 * h1[g] + w2 * h2[g]
                    : 0.f;
            }
            __syncthreads();

            unsigned long long acc[8][4];
#pragma unroll
            for (int r = 0; r < 8; r++)
#pragma unroll
                for (int m = 0; m < 4; m++) acc[r][m] = 0ull;

#pragma unroll
            for (int kk = 0; kk < 64; kk += 4) {
                ulonglong2 w2v[4];
#pragma unroll
                for (int m = 0; m < 4; m++)
                    w2v[m] = *(const ulonglong2*)&Wt[cb + 16 * m][kk];
#pragma unroll
                for (int r = 0; r < 8; r++) {
                    ulonglong2 xv = *(const ulonglong2*)&xs[rg * 8 + r][kk];
#pragma unroll
                    for (int m = 0; m < 4; m++) {
                        ffma2(acc[r][m], xv.x, w2v[m].x);
                        ffma2(acc[r][m], xv.y, w2v[m].y);
                    }
                }
            }
#pragma unroll
            for (int r = 0; r < 8; r++) {
                int row = row0 + rg * 8 + r;
                if (row < NN) {
#pragma unroll
                    for (int m = 0; m < 4; m++) {
                        int c = cb + 16 * m;
                        float v = red2(acc[r][m]);
                        if (khalf == 0) out[row * OUTC + c] = v + fcb[c];
                        else            out[row * OUTC + c] += v;
                    }
                }
            }
        }
    }
}

// ---------------- launch ----------------
extern "C" void kernel_launch(void* const* d_in, const int* in_sizes, int n_in,
                              void* d_out, int out_size) {
    const float* x    = (const float*)d_in[0];
    const int*   ei   = (const int*)d_in[1];
    const float* W1   = (const float*)d_in[2];
    const float* b1   = (const float*)d_in[3];
    const float* W2   = (const float*)d_in[4];
    const float* b2   = (const float*)d_in[5];
    const float* W3   = (const float*)d_in[6];
    const float* b3   = (const float*)d_in[7];
    const float* jkw  = (const float*)d_in[8];
    const float* fcW  = (const float*)d_in[9];
    const float* fcb  = (const float*)d_in[10];
    float* out = (float*)d_out;

    const int* row = ei;        // sources
    const int* col = ei + NE;   // targets

    const int nodeBlocks = (NN + 255) / 256;
    const int edgeBlocks = (NE + 255) / 256;
    const int aggBlocks  = (NN * 32 + 255) / 256;
    const int gemmGrid   = 592;   // 4 CTAs/SM, persistent grid-stride over tiles

    // CSR build (dinv fused into scan)
    zero_k<<<nodeBlocks, 256>>>();
    count_k<<<edgeBlocks, 256>>>(row, col);
    scan_k<<<1, 1024>>>();
    fill_k<<<edgeBlocks, 256>>>(row, col);

    float* tmp  = nullptr; cudaGetSymbolAddress((void**)&tmp,  g_tmp);
    float* hbuf = nullptr; cudaGetSymbolAddress((void**)&hbuf, g_hbuf);
    float* h0m  = nullptr; cudaGetSymbolAddress((void**)&h0m,  g_h0m);
    float* h1   = nullptr; cudaGetSymbolAddress((void**)&h1,   g_h1);
    float* h2   = nullptr; cudaGetSymbolAddress((void**)&h2,   g_h2);

    // layer 0
    gemm128_k<<<gemmGrid, 128>>>(x, W1, tmp);
    agg_gcn_k<<<aggBlocks, 256>>>(tmp, b1, hbuf);
    agg_mean_k<<<aggBlocks, 256>>>(hbuf, h0m);
    // layer 1
    gemm128_k<<<gemmGrid, 128>>>(h0m, W2, tmp);
    agg_gcn_k<<<aggBlocks, 256>>>(tmp, b2, h1);
    // layer 2
    gemm128_k<<<gemmGrid, 128>>>(h1, W3, tmp);
    agg_gcn_k<<<aggBlocks, 256>>>(tmp, b3, h2);
    // JK + head
    final_k<<<gemmGrid, 128>>>(h0m, h1, h2, jkw, fcW, fcb, out);
}